// round 14
// baseline (speedup 1.0000x reference)
#include <cuda_runtime.h>
#include <cuda_fp16.h>
#include <math.h>

#define NN   1024
#define ND   128
#define ED   16
#define MD   64
#define IND  272   // 2*ND + ED
#define CW   512   // fused pre-GEMM width: 64 (HBint) + 64 (HJint) + 384 (GH)

#define EDGE_BLOCKS  148
#define EDGE_THREADS 512
#define EDGE_SMEM    (NN * 32 * 4 + 16 * 64 * 4)   // HJh table + reduction

// ---------------- scratch (no allocations allowed) ----------------
__device__ float g_C   [NN * CW];
__device__ float g_S   [NN * MD];
__device__ float g_deg [NN];
__device__ int   g_idg [NN];
__device__ float g_H1  [NN * ND];
__device__ float g_H2  [NN * ND];
__device__ float g_Wcat[CW * ND];
__device__ float g_bcat[CW];
__device__ float g_Wc  [3 * ND * MD];
__device__ float g_bc  [3 * ND];
__device__ unsigned g_HJh[NN * 32];    // HJ fp16x2 (m, m+32) — 128 KB
// Fixed-stride compacted Ep: row i's edges at [i*1024, i*1024+deg_i)
__device__ unsigned       g_EpC [(size_t)NN * 1024 * 32];
__device__ unsigned short g_Jidx[(size_t)NN * 1024 + 8];

// ---------------- pack kernel ----------------
__global__ void pack_kernel(const float* __restrict__ W1, const float* __restrict__ b1,
                            const float* __restrict__ W_hh, const float* __restrict__ b_hh,
                            float* __restrict__ Wcat, float* __restrict__ bcat)
{
    int idx = blockIdx.x * blockDim.x + threadIdx.x;
    int r = idx >> 7;
    int c = idx & 127;
    float v;
    if (r < MD) {
        int m = (r >> 1) + ((r & 1) << 5);
        v = W1[(size_t)m * IND + c];
    } else if (r < 2 * MD) {
        int rr = r - MD;
        int m = (rr >> 1) + ((rr & 1) << 5);
        v = W1[(size_t)m * IND + ND + c];
    } else {
        v = W_hh[(size_t)(r - 2 * MD) * ND + c];
    }
    Wcat[idx] = v;
    if (idx < CW) {
        float b;
        if (idx < MD) {
            int m = (idx >> 1) + ((idx & 1) << 5);
            b = b1[m];
        }
        else if (idx < 2 * MD) b = 0.f;
        else                   b = b_hh[idx - 2 * MD];
        bcat[idx] = b;
    }
}

// ---------------- Wc = W_ih @ W2, bc = W_ih @ b2 ----------------
__global__ void wc_kernel(const float* __restrict__ W_ih, const float* __restrict__ W2,
                          const float* __restrict__ b2,
                          float* __restrict__ Wc, float* __restrict__ bc)
{
    int bid = blockIdx.x;
    if (bid < 96) {
        int idx = bid * 256 + threadIdx.x;
        int r = idx >> 6;
        int s = idx & 63;
        float acc = 0.f;
        #pragma unroll 8
        for (int m = 0; m < MD; m++)
            acc = fmaf(W_ih[(size_t)r * MD + m], W2[(size_t)m * MD + s], acc);
        Wc[idx] = acc;
    } else {
        for (int r = threadIdx.x; r < 3 * ND; r += blockDim.x) {
            float acc = 0.f;
            #pragma unroll 8
            for (int m = 0; m < MD; m++)
                acc = fmaf(W_ih[(size_t)r * MD + m], b2[m], acc);
            bc[r] = acc;
        }
    }
}

// ---------------- Ep precompute: fixed-stride compacted CSR; also computes deg ----------------
__global__ void ep_kernel(const float* __restrict__ E, const int* __restrict__ A,
                          const float* __restrict__ W1,
                          unsigned* __restrict__ EpC, unsigned short* __restrict__ Jidx,
                          int* __restrict__ idg, float* __restrict__ deg)
{
    const int i    = blockIdx.x;
    const int tid  = threadIdx.x;
    const int w    = tid >> 5;
    const int lane = tid & 31;

    __shared__ float s_e[8][8][16];
    __shared__ int   wcnt[8];

    float we0[ED], we1[ED];
    {
        const float4* p0 = (const float4*)(W1 + (size_t)lane        * IND + 2 * ND);
        const float4* p1 = (const float4*)(W1 + (size_t)(lane + 32) * IND + 2 * ND);
        #pragma unroll
        for (int q = 0; q < 4; q++) {
            float4 v = p0[q];
            we0[4*q+0] = v.x; we0[4*q+1] = v.y; we0[4*q+2] = v.z; we0[4*q+3] = v.w;
            float4 u = p1[q];
            we1[4*q+0] = u.x; we1[4*q+1] = u.y; we1[4*q+2] = u.z; we1[4*q+3] = u.w;
        }
    }

    const int jbase = w * 128;
    const int* Arow = A + (size_t)i * NN + jbase;

    unsigned bal[4];
    int myact = 0;
    #pragma unroll
    for (int s = 0; s < 4; s++) {
        int a = Arow[s * 32 + lane];
        bal[s] = __ballot_sync(0xffffffffu, a != 0);
        myact += __popc(bal[s]);
    }
    if (lane == 0) wcnt[w] = myact;
    __syncthreads();
    int pos = i << 10;                         // fixed row stride 1024
    for (int ww = 0; ww < w; ww++) pos += wcnt[ww];
    if (tid == 0) {
        int t = 0;
        #pragma unroll
        for (int k = 0; k < 8; k++) t += wcnt[k];
        idg[i] = t; deg[i] = (float)t;
    }

    const float4* E4 = (const float4*)(E + ((size_t)i * NN + jbase) * ED);

    for (int c = 0; c < 16; c++) {
        ((float4*)s_e[w])[lane] = E4[c * 32 + lane];
        __syncwarp();
        #pragma unroll
        for (int u = 0; u < 8; u++) {
            int jloc = c * 8 + u;
            if (!((bal[jloc >> 5] >> (jloc & 31)) & 1u)) continue;
            const float4* e4 = (const float4*)s_e[w][u];
            float4 ea = e4[0], eb = e4[1], ec = e4[2], ed = e4[3];
            float v0, v1;
            v0  = ea.x * we0[0];  v1  = ea.x * we1[0];
            v0 = fmaf(ea.y, we0[1],  v0); v1 = fmaf(ea.y, we1[1],  v1);
            v0 = fmaf(ea.z, we0[2],  v0); v1 = fmaf(ea.z, we1[2],  v1);
            v0 = fmaf(ea.w, we0[3],  v0); v1 = fmaf(ea.w, we1[3],  v1);
            v0 = fmaf(eb.x, we0[4],  v0); v1 = fmaf(eb.x, we1[4],  v1);
            v0 = fmaf(eb.y, we0[5],  v0); v1 = fmaf(eb.y, we1[5],  v1);
            v0 = fmaf(eb.z, we0[6],  v0); v1 = fmaf(eb.z, we1[6],  v1);
            v0 = fmaf(eb.w, we0[7],  v0); v1 = fmaf(eb.w, we1[7],  v1);
            v0 = fmaf(ec.x, we0[8],  v0); v1 = fmaf(ec.x, we1[8],  v1);
            v0 = fmaf(ec.y, we0[9],  v0); v1 = fmaf(ec.y, we1[9],  v1);
            v0 = fmaf(ec.z, we0[10], v0); v1 = fmaf(ec.z, we1[10], v1);
            v0 = fmaf(ec.w, we0[11], v0); v1 = fmaf(ec.w, we1[11], v1);
            v0 = fmaf(ed.x, we0[12], v0); v1 = fmaf(ed.x, we1[12], v1);
            v0 = fmaf(ed.y, we0[13], v0); v1 = fmaf(ed.y, we1[13], v1);
            v0 = fmaf(ed.z, we0[14], v0); v1 = fmaf(ed.z, we1[14], v1);
            v0 = fmaf(ed.w, we0[15], v0); v1 = fmaf(ed.w, we1[15], v1);
            unsigned p;
            asm("cvt.rn.f16x2.f32 %0, %1, %2;" : "=r"(p) : "f"(v1), "f"(v0));
            __stcg(&EpC[(size_t)pos * 32 + lane], p);
            if (lane == 0) Jidx[pos] = (unsigned short)(jbase + jloc);
            pos++;
        }
        __syncwarp();
    }
}

// ---------------- GEMM: 32x32 tile, 256 threads, 2x2 micro (occupancy-first) ----------------
// C = A @ W^T + bias (+ HJh emit). Grid: (p/32, n/32).
template<int K>
__global__ void gemm_kernel(const float* __restrict__ A, int lda,
                            const float* __restrict__ W, int ldw,
                            const float* __restrict__ bias,
                            float* __restrict__ C, int ldc,
                            unsigned* __restrict__ HJh)
{
    __shared__ float As[2][32][36];     // [buf][kk][row]
    __shared__ float Ws[2][32][36];     // [buf][kk][col]
    constexpr int NC = K / 32;
    const int tid  = threadIdx.x;
    const int row0 = blockIdx.y * 32;
    const int col0 = blockIdx.x * 32;
    const int tr = (tid >> 4) * 2;      // 0..30
    const int tc = (tid & 15) * 2;      // 0..30
    const int ar = tid >> 3;            // 0..31
    const int ac = (tid & 7) * 4;       // 0..28

    float acc[2][2] = {};

    {
        float4 av = *(const float4*)&A[(size_t)(row0 + ar) * lda + ac];
        As[0][ac+0][ar] = av.x; As[0][ac+1][ar] = av.y;
        As[0][ac+2][ar] = av.z; As[0][ac+3][ar] = av.w;
        float4 wv = *(const float4*)&W[(size_t)(col0 + ar) * ldw + ac];
        Ws[0][ac+0][ar] = wv.x; Ws[0][ac+1][ar] = wv.y;
        Ws[0][ac+2][ar] = wv.z; Ws[0][ac+3][ar] = wv.w;
    }
    __syncthreads();

    int buf = 0;
    #pragma unroll
    for (int c0 = 0; c0 < NC; c0++) {
        float4 pa, pw;
        if (c0 + 1 < NC) {
            pa = *(const float4*)&A[(size_t)(row0 + ar) * lda + (c0 + 1) * 32 + ac];
            pw = *(const float4*)&W[(size_t)(col0 + ar) * ldw + (c0 + 1) * 32 + ac];
        }
        #pragma unroll
        for (int kk = 0; kk < 32; kk++) {
            float2 a2 = *(const float2*)&As[buf][kk][tr];
            float2 b2 = *(const float2*)&Ws[buf][kk][tc];
            acc[0][0] = fmaf(a2.x, b2.x, acc[0][0]); acc[0][1] = fmaf(a2.x, b2.y, acc[0][1]);
            acc[1][0] = fmaf(a2.y, b2.x, acc[1][0]); acc[1][1] = fmaf(a2.y, b2.y, acc[1][1]);
        }
        if (c0 + 1 < NC) {
            As[buf^1][ac+0][ar] = pa.x; As[buf^1][ac+1][ar] = pa.y;
            As[buf^1][ac+2][ar] = pa.z; As[buf^1][ac+3][ar] = pa.w;
            Ws[buf^1][ac+0][ar] = pw.x; Ws[buf^1][ac+1][ar] = pw.y;
            Ws[buf^1][ac+2][ar] = pw.z; Ws[buf^1][ac+3][ar] = pw.w;
            __syncthreads();
            buf ^= 1;
        }
    }

    const bool emit_hj = (HJh != nullptr) && (col0 >= MD) && (col0 < 2 * MD);
    #pragma unroll
    for (int r = 0; r < 2; r++) {
        int row = row0 + tr + r;
        float v0 = acc[r][0], v1 = acc[r][1];
        int c0i = col0 + tc, c1i = col0 + tc + 1;
        if (bias) { v0 += bias[c0i]; v1 += bias[c1i]; }
        C[(size_t)row * ldc + c0i] = v0;
        C[(size_t)row * ldc + c1i] = v1;
        if (emit_hj) {
            int m = (col0 + tc - MD) >> 1;
            unsigned p;
            asm("cvt.rn.f16x2.f32 %0, %1, %2;" : "=r"(p) : "f"(v1), "f"(v0));
            HJh[row * 32 + m] = p;
        }
    }
}

// ---------------- edge kernel: persistent blocks + smem-staged HJh ----------------
// 148 blocks x 512 threads; block stages the 128 KB HJh table once, then
// processes rows bid, bid+148, ... Ep streamed via __ldcg (L2).
__global__ void edge_kernel(const float* __restrict__ C,
                            const unsigned* __restrict__ HJh,
                            const unsigned* __restrict__ EpC,
                            const unsigned short* __restrict__ Jidx,
                            const int* __restrict__ idg,
                            float* __restrict__ S)
{
    extern __shared__ unsigned sm[];
    unsigned* sm_hj = sm;                       // NN*32 u32 = 128 KB
    float*    s_red = (float*)(sm + NN * 32);   // 16*64 floats

    const int tid  = threadIdx.x;
    const int w    = tid >> 5;     // 0..15
    const int lane = tid & 31;

    // stage HJh table (coalesced uint4)
    {
        const uint4* src = (const uint4*)HJh;
        uint4*       dst = (uint4*)sm_hj;
        #pragma unroll 4
        for (int k = tid; k < NN * 32 / 4; k += EDGE_THREADS)
            dst[k] = src[k];
    }
    __syncthreads();

    for (int i = blockIdx.x; i < NN; i += EDGE_BLOCKS) {
        const float2 hb2 = *(const float2*)(C + (size_t)i * CW + 2 * lane);
        const int cnt   = idg[i];
        const size_t base = (size_t)i << 10;
        const unsigned*       ep = EpC + base * 32;
        const unsigned short* jx = Jidx + base;

        float acc0 = 0.f, acc1 = 0.f;

        for (int cb = w * 8; cb < cnt; cb += 128) {   // 16 warps x 8 edges
            int nrem = cnt - cb;
            int jv[8];
            {
                ushort4 ja = *(const ushort4*)(jx + cb);
                jv[0]=ja.x; jv[1]=ja.y; jv[2]=ja.z; jv[3]=ja.w;
                if (nrem > 4) {
                    ushort4 jb = *(const ushort4*)(jx + cb + 4);
                    jv[4]=jb.x; jv[5]=jb.y; jv[6]=jb.z; jv[7]=jb.w;
                } else { jv[4]=jv[5]=jv[6]=jv[7]=0; }
            }
            unsigned pe[8], ph[8];
            #pragma unroll
            for (int u = 0; u < 8; u++) {
                if (u < nrem) {
                    pe[u] = __ldcg(&ep[(size_t)(cb + u) * 32 + lane]);  // L2 stream
                    ph[u] = sm_hj[jv[u] * 32 + lane];                   // LDS, conflict-free
                }
            }
            #pragma unroll
            for (int u = 0; u < 8; u++) {
                if (u < nrem) {
                    float2 ef = __half22float2(*(const __half2*)&pe[u]);
                    float2 hf = __half22float2(*(const __half2*)&ph[u]);
                    acc0 += fmaxf(hb2.x + hf.x + ef.x, 0.f);
                    acc1 += fmaxf(hb2.y + hf.y + ef.y, 0.f);
                }
            }
        }

        s_red[w * 64 + lane]      = acc0;
        s_red[w * 64 + lane + 32] = acc1;
        __syncthreads();
        if (tid < MD) {
            float s = 0.f;
            #pragma unroll
            for (int ww = 0; ww < 16; ww++) s += s_red[ww * 64 + tid];
            S[i * MD + tid] = s;
        }
        __syncthreads();
    }
}

// ---------------- fused GI + GRU kernel ----------------
__global__ void gi_gru_kernel(const float* __restrict__ S,
                              const float* __restrict__ Wc,
                              const float* __restrict__ b_ih,
                              const float* __restrict__ bc,
                              const float* __restrict__ deg,
                              const float* __restrict__ C,
                              const float* __restrict__ Hprev,
                              float* __restrict__ Hout)
{
    __shared__ float As[32][36];        // [kk][node]
    __shared__ float Wg[32][3][33];     // [kk][gate][d]

    const int tid = threadIdx.x;
    const int d0  = blockIdx.x * 32;
    const int i0  = blockIdx.y * 32;
    const int rg  = tid >> 5;
    const int dl  = tid & 31;
    const int d   = d0 + dl;

    float accr[4] = {}, accz[4] = {}, accn[4] = {};

    #pragma unroll
    for (int c0 = 0; c0 < 2; c0++) {
        {
            int srow = tid >> 3;
            int kq   = (tid & 7) * 4;
            float4 v = *(const float4*)&S[(size_t)(i0 + srow) * MD + c0 * 32 + kq];
            As[kq+0][srow] = v.x; As[kq+1][srow] = v.y;
            As[kq+2][srow] = v.z; As[kq+3][srow] = v.w;
        }
        #pragma unroll
        for (int l = 0; l < 3; l++) {
            int s    = tid + l * 256;
            int r96  = s >> 3;
            int kq   = (s & 7) * 4;
            int gate = r96 >> 5;
            int dd   = r96 & 31;
            int grow = gate * ND + d0 + dd;
            float4 v = *(const float4*)&Wc[(size_t)grow * MD + c0 * 32 + kq];
            Wg[kq+0][gate][dd] = v.x; Wg[kq+1][gate][dd] = v.y;
            Wg[kq+2][gate][dd] = v.z; Wg[kq+3][gate][dd] = v.w;
        }
        __syncthreads();
        #pragma unroll
        for (int kk = 0; kk < 32; kk++) {
            float4 a4 = *(const float4*)&As[kk][rg * 4];
            float br = Wg[kk][0][dl], bz = Wg[kk][1][dl], bn = Wg[kk][2][dl];
            accr[0] = fmaf(a4.x, br, accr[0]); accz[0] = fmaf(a4.x, bz, accz[0]); accn[0] = fmaf(a4.x, bn, accn[0]);
            accr[1] = fmaf(a4.y, br, accr[1]); accz[1] = fmaf(a4.y, bz, accz[1]); accn[1] = fmaf(a4.y, bn, accn[1]);
            accr[2] = fmaf(a4.z, br, accr[2]); accz[2] = fmaf(a4.z, bz, accz[2]); accn[2] = fmaf(a4.z, bn, accn[2]);
            accr[3] = fmaf(a4.w, br, accr[3]); accz[3] = fmaf(a4.w, bz, accz[3]); accn[3] = fmaf(a4.w, bn, accn[3]);
        }
        __syncthreads();
    }

    const float bir = b_ih[d], biz = b_ih[ND + d], bin = b_ih[2 * ND + d];
    const float bcr = bc[d],  bcz = bc[ND + d],  bcn = bc[2 * ND + d];

    #pragma unroll
    for (int q = 0; q < 4; q++) {
        int row = i0 + rg * 4 + q;
        float dg = deg[row];
        float gir = accr[q] + bir + dg * bcr;
        float giz = accz[q] + biz + dg * bcz;
        float gin = accn[q] + bin + dg * bcn;
        const float* gh = C + (size_t)row * CW + 2 * MD;
        float ghr = gh[d], ghz = gh[ND + d], ghn = gh[2 * ND + d];
        float r = 1.f / (1.f + __expf(-(gir + ghr)));
        float z = 1.f / (1.f + __expf(-(giz + ghz)));
        float narg = gin + r * ghn;
        float n = 1.f - 2.f / (__expf(2.f * narg) + 1.f);
        float h = Hprev[(size_t)row * ND + d];
        Hout[(size_t)row * ND + d] = (1.f - z) * n + z * h;
    }
}

// ---------------- launch ----------------
extern "C" void kernel_launch(void* const* d_in, const int* in_sizes, int n_in,
                              void* d_out, int out_size)
{
    const float* X    = (const float*)d_in[0];
    const int*   A    = (const int*)  d_in[1];
    const float* E    = (const float*)d_in[2];
    const float* W1   = (const float*)d_in[3];
    const float* b1   = (const float*)d_in[4];
    const float* W2   = (const float*)d_in[5];
    const float* b2   = (const float*)d_in[6];
    const float* W_ih = (const float*)d_in[7];
    const float* b_ih = (const float*)d_in[8];
    const float* W_hh = (const float*)d_in[9];
    const float* b_hh = (const float*)d_in[10];

    float *C, *S, *DEG, *H1, *H2, *Wcat, *bcat, *Wc, *bc;
    int *IDG;
    unsigned *EPC, *HJH;
    unsigned short* JIDX;
    cudaGetSymbolAddress((void**)&C,    g_C);
    cudaGetSymbolAddress((void**)&S,    g_S);
    cudaGetSymbolAddress((void**)&DEG,  g_deg);
    cudaGetSymbolAddress((void**)&IDG,  g_idg);
    cudaGetSymbolAddress((void**)&H1,   g_H1);
    cudaGetSymbolAddress((void**)&H2,   g_H2);
    cudaGetSymbolAddress((void**)&Wcat, g_Wcat);
    cudaGetSymbolAddress((void**)&bcat, g_bcat);
    cudaGetSymbolAddress((void**)&Wc,   g_Wc);
    cudaGetSymbolAddress((void**)&bc,   g_bc);
    cudaGetSymbolAddress((void**)&EPC,  g_EpC);
    cudaGetSymbolAddress((void**)&HJH,  g_HJh);
    cudaGetSymbolAddress((void**)&JIDX, g_Jidx);

    // allow 132 KB dynamic smem for the edge kernel (idempotent)
    cudaFuncSetAttribute(edge_kernel, cudaFuncAttributeMaxDynamicSharedMemorySize,
                         EDGE_SMEM);

    // one-time (per call) precomputes
    pack_kernel<<<(CW * ND) / 256, 256>>>(W1, b1, W_hh, b_hh, Wcat, bcat);
    wc_kernel<<<97, 256>>>(W_ih, W2, b2, Wc, bc);
    ep_kernel<<<NN, 256>>>(E, A, W1, EPC, JIDX, IDG, DEG);

    const float* Hprev = X;
    for (int t = 0; t < 3; t++) {
        float* Hout = (t == 2) ? (float*)d_out : (t == 0 ? H1 : H2);

        // C = Hprev @ Wcat^T + bcat -> [HBint | HJint | GH]; HJh emitted in epilogue
        gemm_kernel<128><<<dim3(CW / 32, NN / 32), 256>>>(Hprev, ND, Wcat, ND, bcat,
                                                          C, CW, HJH);

        // relu-sum over compacted edges (persistent, smem-staged HJh)
        edge_kernel<<<EDGE_BLOCKS, EDGE_THREADS, EDGE_SMEM>>>(C, HJH, EPC, JIDX, IDG, S);

        // fused GI + GRU -> Hout
        gi_gru_kernel<<<dim3(4, 32), 256>>>(S, Wc, b_ih, bc, DEG, C, Hprev, Hout);

        Hprev = Hout;
    }
}